// round 16
// baseline (speedup 1.0000x reference)
#include <cuda_runtime.h>
#include <math.h>

#define N_ 128
#define H_ 256
#define B_ 16

// -------- device scratch --------
__device__ float g_P[H_*H_];        // W1^T W1
__device__ float g_Q[H_*H_];        // W2 W2^T
__device__ float g_s[B_*H_];
__device__ float g_c[B_*H_];
__device__ float g_Avec[B_*N_];
__device__ float g_Cvec[B_*N_];
__device__ float g_vn[B_];
__device__ float g_A2[B_*H_*H_];    // A2 = P S Q (RED-accumulated, zeroed in stage1)
__device__ float g_part[B_*20];     // nrm^2/2 partials: [b][tile*2+ka]
__device__ unsigned int g_cnt[B_];  // last-block-done counters

#define FFMA2(d, a, b) \
    asm("fma.rn.f32x2 %0, %1, %2, %0;" : "+l"(d) : "l"(a), "l"(b))
#define DUP2(d, f) \
    asm("mov.b64 %0, {%1, %1};" : "=l"(d) : "f"(f))
#define UNPK2(lo, hi, d) \
    asm("mov.b64 {%0, %1}, %2;" : "=f"(lo), "=f"(hi) : "l"(d))

#define MICRO_STEP_F32X2(As_, Bs_)                                      \
    {   float4 ra = *(const float4*)&As_[k][ty*4];                      \
        ulonglong2 rbp = *(const ulonglong2*)&Bs_[k][tx*4];             \
        unsigned long long ad0, ad1, ad2, ad3;                          \
        DUP2(ad0, ra.x); DUP2(ad1, ra.y);                               \
        DUP2(ad2, ra.z); DUP2(ad3, ra.w);                               \
        FFMA2(accp[0][0], ad0, rbp.x); FFMA2(accp[0][1], ad0, rbp.y);   \
        FFMA2(accp[1][0], ad1, rbp.x); FFMA2(accp[1][1], ad1, rbp.y);   \
        FFMA2(accp[2][0], ad2, rbp.x); FFMA2(accp[2][1], ad2, rbp.y);   \
        FFMA2(accp[3][0], ad3, rbp.x); FFMA2(accp[3][1], ad3, rbp.y);   \
    }

#define UNPACK_ACC()                                                    \
    float acc[4][4];                                                    \
    _Pragma("unroll")                                                   \
    for (int i = 0; i < 4; i++){                                        \
        UNPK2(acc[i][0], acc[i][1], accp[i][0]);                        \
        UNPK2(acc[i][2], acc[i][3], accp[i][1]);                        \
    }

#define LOAD16_ROW(dst, ptr)                                            \
    {   float4 t0 = *(const float4*)&(ptr)[0];                          \
        float4 t1 = *(const float4*)&(ptr)[4];                          \
        float4 t2 = *(const float4*)&(ptr)[8];                          \
        float4 t3 = *(const float4*)&(ptr)[12];                         \
        dst[0]=t0.x; dst[1]=t0.y; dst[2]=t0.z; dst[3]=t0.w;             \
        dst[4]=t1.x; dst[5]=t1.y; dst[6]=t1.z; dst[7]=t1.w;             \
        dst[8]=t2.x; dst[9]=t2.y; dst[10]=t2.z; dst[11]=t2.w;           \
        dst[12]=t3.x; dst[13]=t3.y; dst[14]=t3.z; dst[15]=t3.w;         \
    }

// ==================== stage 1: P/Q GEMM + s,c,vn + A2 zeroing ====================
// blocks 0..31: P/Q tiles; 32..47: per-sample s/c/vn; 48..111: zero g_A2.
__global__ void __launch_bounds__(256) k_stage1(
        const float* __restrict__ W1, const float* __restrict__ W2,
        const float* __restrict__ tptr, const float* __restrict__ state,
        const float* __restrict__ x0,  const float* __restrict__ x1,
        const float* __restrict__ b1){
    int bid = blockIdx.x;
    int tid = threadIdx.x;

    if (bid >= 48){
        // zero g_A2: 64 blocks x 256 thr x 16 float4 = 4MB
        int zb = bid - 48;
        float4* dst = (float4*)g_A2 + zb*4096;
        float4 zz = make_float4(0.f, 0.f, 0.f, 0.f);
        #pragma unroll
        for (int i = 0; i < 16; i++)
            dst[i*256 + tid] = zz;
        return;
    }

    if (bid < 32){
        int z = bid >> 4, tile = bid & 15;
        int g0 = (tile >> 2)*64, h0 = (tile & 3)*64;
        __shared__ float As[2][16][68];
        __shared__ float Bs[2][16][68];
        int ty = tid >> 4, tx = tid & 15;
        unsigned long long accp[4][2] = {{0ull,0ull},{0ull,0ull},{0ull,0ull},{0ull,0ull}};

        int la = tid >> 4, lq4 = (tid & 15)*4;
        int gg = tid >> 2, kq = (tid & 3)*4;
        float4 av, bv;
        if (z == 0){
            av = *(const float4*)&W1[la*H_ + g0 + lq4];
            bv = *(const float4*)&W1[la*H_ + h0 + lq4];
            *(float4*)&As[0][la][lq4] = av;
            *(float4*)&Bs[0][la][lq4] = bv;
        } else {
            av = *(const float4*)&W2[(g0+gg)*N_ + kq];
            bv = *(const float4*)&W2[(h0+gg)*N_ + kq];
            As[0][kq+0][gg] = av.x; As[0][kq+1][gg] = av.y;
            As[0][kq+2][gg] = av.z; As[0][kq+3][gg] = av.w;
            Bs[0][kq+0][gg] = bv.x; Bs[0][kq+1][gg] = bv.y;
            Bs[0][kq+2][gg] = bv.z; Bs[0][kq+3][gg] = bv.w;
        }
        __syncthreads();

        for (int t = 0; t < 8; t++){
            int cur = t & 1;
            if (t < 7){
                int a0 = (t+1)*16;
                if (z == 0){
                    av = *(const float4*)&W1[(a0+la)*H_ + g0 + lq4];
                    bv = *(const float4*)&W1[(a0+la)*H_ + h0 + lq4];
                } else {
                    av = *(const float4*)&W2[(g0+gg)*N_ + a0 + kq];
                    bv = *(const float4*)&W2[(h0+gg)*N_ + a0 + kq];
                }
            }
            #pragma unroll
            for (int k = 0; k < 16; k++) MICRO_STEP_F32X2(As[cur], Bs[cur])
            if (t < 7){
                if (z == 0){
                    *(float4*)&As[cur^1][la][lq4] = av;
                    *(float4*)&Bs[cur^1][la][lq4] = bv;
                } else {
                    As[cur^1][kq+0][gg] = av.x; As[cur^1][kq+1][gg] = av.y;
                    As[cur^1][kq+2][gg] = av.z; As[cur^1][kq+3][gg] = av.w;
                    Bs[cur^1][kq+0][gg] = bv.x; Bs[cur^1][kq+1][gg] = bv.y;
                    Bs[cur^1][kq+2][gg] = bv.z; Bs[cur^1][kq+3][gg] = bv.w;
                }
            }
            __syncthreads();
        }
        UNPACK_ACC()
        float* dst = (z == 0) ? g_P : g_Q;
        #pragma unroll
        for (int i = 0; i < 4; i++){
            float4 o = make_float4(acc[i][0], acc[i][1], acc[i][2], acc[i][3]);
            *(float4*)&dst[(g0+ty*4+i)*H_ + h0 + tx*4] = o;
        }
        return;
    }

    // ---- per-sample: x, u = W1^T x, s, c, ||v|| ----
    int b = bid - 32;
    __shared__ float xs[N_], red[N_];
    if (tid == 0) g_cnt[b] = 0;     // reset for k_nrm

    float tval = *tptr;
    float window = 4.f * tval * (1.f - tval);
    if (tid < N_){
        float dev = state[b*N_ + tid];
        float v   = state[(B_+b)*N_ + tid];
        float x0v = x0[b*N_ + tid];
        xs[tid] = x0v + tval*(x1[b*N_ + tid] - x0v) + window*dev;
        red[tid] = v*v;
    }
    __syncthreads();

    if (tid < 32){
        float a0 = red[tid] + red[tid+32] + red[tid+64] + red[tid+96];
        #pragma unroll
        for (int o = 16; o; o >>= 1) a0 += __shfl_xor_sync(0xffffffffu, a0, o);
        if (tid == 0) g_vn[b] = sqrtf(a0);
    }

    int h = tid;
    float u = 0.f;
    for (int k0 = 0; k0 < N_; k0 += 16){
        float wb[16];
        #pragma unroll
        for (int j = 0; j < 16; j++) wb[j] = W1[(k0+j)*H_ + h];
        #pragma unroll
        for (int j = 0; j < 16; j++) u += xs[k0+j]*wb[j];
    }
    float th = tanhf(u + b1[h]);
    float s = 1.f - th*th;
    g_s[b*H_ + h] = s;
    g_c[b*H_ + h] = -2.f*th*s;
}

// ========== stage 2: z==0 -> vector part 2; z>=1 -> split-K A2 GEMM (RED out) ==========
__global__ void __launch_bounds__(256) k_A2(
        const float* __restrict__ W1, const float* __restrict__ W2,
        const float* __restrict__ state){
    int tid = threadIdx.x;
    if (blockIdx.z == 0){
        // ---- vector part 2: w,y -> z,q2 via P -> pv,cwz -> A,C ----
        int b = blockIdx.y*4 + blockIdx.x;
        __shared__ float vs[N_];
        __shared__ float swv[H_], cwy[H_], pvs[H_], cwz[H_];
        __shared__ float Ap[2][N_], Cp[2][N_];

        if (tid < N_) vs[tid] = state[(B_+b)*N_ + tid];
        __syncthreads();

        int h = tid;
        float s = g_s[b*H_ + h];
        float c = g_c[b*H_ + h];
        float w = 0.f, y = 0.f;
        {
            const float* w2r = W2 + h*N_;
            for (int k0 = 0; k0 < N_; k0 += 16){
                float tb[16], wb[16];
                LOAD16_ROW(tb, (w2r + k0))
                #pragma unroll
                for (int j = 0; j < 16; j++) wb[j] = W1[(k0+j)*H_ + h];
                #pragma unroll
                for (int j = 0; j < 16; j++){
                    w += vs[k0+j]*tb[j];
                    y += vs[k0+j]*wb[j];
                }
            }
        }
        swv[h] = s*w;
        cwy[h] = c*w*y;
        __syncthreads();

        float z = 0.f, q2 = 0.f;
        for (int a0 = 0; a0 < H_; a0 += 16){
            float pb[16];
            #pragma unroll
            for (int j = 0; j < 16; j++) pb[j] = g_P[(a0+j)*H_ + h];
            #pragma unroll
            for (int j = 0; j < 16; j++){
                z  += pb[j]*swv[a0+j];
                q2 += pb[j]*cwy[a0+j];
            }
        }
        pvs[h] = c*y*z + s*q2;
        cwz[h] = c*w*z;
        __syncthreads();

        {
            int i = tid & 127, hf = tid >> 7;
            const float* w1r = W1 + i*H_ + hf*128;
            float A = 0.f, Cc = 0.f;
            for (int j0 = 0; j0 < 128; j0 += 16){
                float wa[16], wc[16];
                #pragma unroll
                for (int j = 0; j < 16; j++) wa[j] = W2[(hf*128 + j0 + j)*N_ + i];
                LOAD16_ROW(wc, (w1r + j0))
                #pragma unroll
                for (int j = 0; j < 16; j++){
                    A  += wa[j]*pvs[hf*128 + j0 + j];
                    Cc += wc[j]*cwz[hf*128 + j0 + j];
                }
            }
            Ap[hf][i] = A;
            Cp[hf][i] = Cc;
        }
        __syncthreads();
        if (tid < N_){
            g_Avec[b*N_ + tid] = Ap[0][tid] + Ap[1][tid];
            g_Cvec[b*N_ + tid] = 2.f*(Cp[0][tid] + Cp[1][tid]);
        }
        return;
    }

    // ---- split-K A2 GEMM, K-chunk 32, RED-accumulated output ----
    int zz = blockIdx.z - 1;
    int b = zz >> 1, ka = zz & 1;
    int g0 = blockIdx.y*64, h0 = blockIdx.x*64;
    int ty = tid >> 4, tx = tid & 15;
    __shared__ float Ps[2][32][68];
    __shared__ float Qs[2][32][68];
    __shared__ float ssm[H_];
    ssm[tid] = g_s[b*H_ + tid];
    unsigned long long accp[4][2] = {{0ull,0ull},{0ull,0ull},{0ull,0ull},{0ull,0ull}};

    int a = tid >> 4, q4 = (tid & 15)*4;
    int abase = ka*128;
    float4 pv0 = *(const float4*)&g_P[(abase + a)*H_ + g0 + q4];
    float4 pv1 = *(const float4*)&g_P[(abase + a + 16)*H_ + g0 + q4];
    float4 qv0 = *(const float4*)&g_Q[(abase + a)*H_ + h0 + q4];
    float4 qv1 = *(const float4*)&g_Q[(abase + a + 16)*H_ + h0 + q4];
    __syncthreads();            // ssm ready
    {
        float s0 = ssm[abase + a], s1 = ssm[abase + a + 16];
        *(float4*)&Ps[0][a][q4] = pv0;
        *(float4*)&Ps[0][a+16][q4] = pv1;
        qv0.x *= s0; qv0.y *= s0; qv0.z *= s0; qv0.w *= s0;
        qv1.x *= s1; qv1.y *= s1; qv1.z *= s1; qv1.w *= s1;
        *(float4*)&Qs[0][a][q4] = qv0;
        *(float4*)&Qs[0][a+16][q4] = qv1;
    }
    __syncthreads();

    for (int t = 0; t < 4; t++){
        int cur = t & 1;
        if (t < 3){
            int a0 = abase + (t+1)*32;
            pv0 = *(const float4*)&g_P[(a0 + a)*H_ + g0 + q4];
            pv1 = *(const float4*)&g_P[(a0 + a + 16)*H_ + g0 + q4];
            qv0 = *(const float4*)&g_Q[(a0 + a)*H_ + h0 + q4];
            qv1 = *(const float4*)&g_Q[(a0 + a + 16)*H_ + h0 + q4];
        }
        #pragma unroll
        for (int k = 0; k < 32; k++) MICRO_STEP_F32X2(Ps[cur], Qs[cur])
        if (t < 3){
            int a0 = abase + (t+1)*32;
            float s0 = ssm[a0 + a], s1 = ssm[a0 + a + 16];
            *(float4*)&Ps[cur^1][a][q4] = pv0;
            *(float4*)&Ps[cur^1][a+16][q4] = pv1;
            qv0.x *= s0; qv0.y *= s0; qv0.z *= s0; qv0.w *= s0;
            qv1.x *= s1; qv1.y *= s1; qv1.z *= s1; qv1.w *= s1;
            *(float4*)&Qs[cur^1][a][q4] = qv0;
            *(float4*)&Qs[cur^1][a+16][q4] = qv1;
        }
        __syncthreads();
    }
    UNPACK_ACC()
    // exactly 2 contributions per element (ka=0,1); fp add commutative -> deterministic
    float* dst = g_A2 + b*H_*H_;
    #pragma unroll
    for (int i = 0; i < 4; i++)
        #pragma unroll
        for (int j = 0; j < 4; j++)
            atomicAdd(&dst[(g0+ty*4+i)*H_ + h0 + tx*4 + j], acc[i][j]);
}

// ========== stage 3: M = P diag(s) A2^T, upper tiles x split-K2, K-chunk 32 ==========
__global__ void __launch_bounds__(256) k_nrm(const float* __restrict__ state,
                                             float* __restrict__ out){
    const int gt_t[10] = {0,0,0,0,1,1,1,2,2,3};
    const int ht_t[10] = {0,1,2,3,1,2,3,2,3,3};
    int b  = blockIdx.z;
    int ti = blockIdx.x;
    int ka = blockIdx.y;
    int g0 = gt_t[ti]*64, h0 = ht_t[ti]*64;
    int abase = ka*128;
    bool diag = (g0 == h0);
    int tid = threadIdx.x;
    int ty = tid >> 4, tx = tid & 15;
    __shared__ float As[2][32][68];
    __shared__ float Bs[2][32][68];
    __shared__ float Ts[64][65];
    __shared__ float ssm[H_];
    ssm[tid] = g_s[b*H_ + tid];
    unsigned long long accp[4][2] = {{0ull,0ull},{0ull,0ull},{0ull,0ull},{0ull,0ull}};

    const float* A2b = g_A2 + b*H_*H_;
    int a  = tid >> 4, q4 = (tid & 15)*4;
    int rw = tid >> 2, kq = (tid & 3)*4;

    if (ka == 0){
        #pragma unroll
        for (int p = 0; p < 4; p++){
            int f = tid + p*256;
            int row = f >> 4, c4 = (f & 15)*4;
            float4 tv = *(const float4*)&A2b[(h0+row)*H_ + g0 + c4];
            Ts[row][c4+0] = tv.x; Ts[row][c4+1] = tv.y;
            Ts[row][c4+2] = tv.z; Ts[row][c4+3] = tv.w;
        }
    }

    float4 pv0 = *(const float4*)&g_P[(abase + a)*H_ + g0 + q4];
    float4 pv1 = *(const float4*)&g_P[(abase + a + 16)*H_ + g0 + q4];
    float4 bv0 = *(const float4*)&A2b[(h0+rw)*H_ + abase + kq];
    float4 bv1 = *(const float4*)&A2b[(h0+rw)*H_ + abase + 16 + kq];
    __syncthreads();
    {
        float s0 = ssm[abase + a], s1 = ssm[abase + a + 16];
        pv0.x *= s0; pv0.y *= s0; pv0.z *= s0; pv0.w *= s0;
        pv1.x *= s1; pv1.y *= s1; pv1.z *= s1; pv1.w *= s1;
        *(float4*)&As[0][a][q4] = pv0;
        *(float4*)&As[0][a+16][q4] = pv1;
        Bs[0][kq+0][rw] = bv0.x; Bs[0][kq+1][rw] = bv0.y;
        Bs[0][kq+2][rw] = bv0.z; Bs[0][kq+3][rw] = bv0.w;
        Bs[0][kq+16][rw] = bv1.x; Bs[0][kq+17][rw] = bv1.y;
        Bs[0][kq+18][rw] = bv1.z; Bs[0][kq+19][rw] = bv1.w;
    }
    __syncthreads();

    for (int t = 0; t < 4; t++){
        int cur = t & 1;
        if (t < 3){
            int a0 = abase + (t+1)*32;
            pv0 = *(const float4*)&g_P[(a0 + a)*H_ + g0 + q4];
            pv1 = *(const float4*)&g_P[(a0 + a + 16)*H_ + g0 + q4];
            bv0 = *(const float4*)&A2b[(h0+rw)*H_ + a0 + kq];
            bv1 = *(const float4*)&A2b[(h0+rw)*H_ + a0 + 16 + kq];
        }
        #pragma unroll
        for (int k = 0; k < 32; k++) MICRO_STEP_F32X2(As[cur], Bs[cur])
        if (t < 3){
            int a0 = abase + (t+1)*32;
            float s0 = ssm[a0 + a], s1 = ssm[a0 + a + 16];
            pv0.x *= s0; pv0.y *= s0; pv0.z *= s0; pv0.w *= s0;
            pv1.x *= s1; pv1.y *= s1; pv1.z *= s1; pv1.w *= s1;
            *(float4*)&As[cur^1][a][q4] = pv0;
            *(float4*)&As[cur^1][a+16][q4] = pv1;
            Bs[cur^1][kq+0][rw] = bv0.x; Bs[cur^1][kq+1][rw] = bv0.y;
            Bs[cur^1][kq+2][rw] = bv0.z; Bs[cur^1][kq+3][rw] = bv0.w;
            Bs[cur^1][kq+16][rw] = bv1.x; Bs[cur^1][kq+17][rw] = bv1.y;
            Bs[cur^1][kq+18][rw] = bv1.z; Bs[cur^1][kq+19][rw] = bv1.w;
        }
        __syncthreads();
    }
    UNPACK_ACC()

    const float* cb = g_c + b*H_;
    float local = 0.f;
    #pragma unroll
    for (int i = 0; i < 4; i++){
        int g = g0 + ty*4 + i;
        float cg = cb[g];
        float4 P4  = *(const float4*)&g_P[g*H_ + h0 + tx*4];
        float4 Q4  = *(const float4*)&g_Q[g*H_ + h0 + tx*4];
        float pr[4] = {P4.x, P4.y, P4.z, P4.w};
        float qr[4] = {Q4.x, Q4.y, Q4.z, Q4.w};
        if (ka == 0){
            float4 A4 = *(const float4*)&A2b[g*H_ + h0 + tx*4];
            float ar[4] = {A4.x, A4.y, A4.z, A4.w};
            #pragma unroll
            for (int j = 0; j < 4; j++){
                int hcol = h0 + tx*4 + j;
                float wgt = diag ? ((hcol > g) ? 2.f : ((hcol == g) ? 1.f : 0.f)) : 2.f;
                float a2t = Ts[tx*4+j][ty*4+i];
                local += wgt*cg*cb[hcol]*pr[j]*(qr[j]*acc[i][j] + ar[j]*a2t);
            }
        } else {
            #pragma unroll
            for (int j = 0; j < 4; j++){
                int hcol = h0 + tx*4 + j;
                float wgt = diag ? ((hcol > g) ? 2.f : ((hcol == g) ? 1.f : 0.f)) : 2.f;
                local += wgt*cg*cb[hcol]*pr[j]*qr[j]*acc[i][j];
            }
        }
    }
    __shared__ float red[256];
    red[tid] = local;
    __syncthreads();
    for (int st = 128; st > 0; st >>= 1){
        if (tid < st) red[tid] += red[tid + st];
        __syncthreads();
    }
    __shared__ unsigned int is_last;
    if (tid == 0){
        g_part[b*20 + ti*2 + ka] = red[0];
        __threadfence();
        is_last = (atomicAdd(&g_cnt[b], 1u) == 19u);
    }
    __syncthreads();

    if (is_last && tid < N_){
        float sum = 0.f;
        #pragma unroll
        for (int i = 0; i < 20; i++) sum += g_part[b*20 + i];
        float nrm = sqrtf(fmaxf(2.f*sum, 0.f));
        float vn  = g_vn[b];
        float v   = state[(B_+b)*N_ + tid];
        float dev = state[b*N_ + tid];
        float aout = -(g_Avec[b*N_ + tid] - 0.5f*g_Cvec[b*N_ + tid])
                     / ((nrm + 1e-6f) * (vn + 1e-6f));
        out[b*N_ + tid]       = v;
        out[(B_+b)*N_ + tid]  = aout - 0.1f*dev;
    }
}

// -------- launch --------
extern "C" void kernel_launch(void* const* d_in, const int* in_sizes, int n_in,
                              void* d_out, int out_size){
    const float* t     = (const float*)d_in[0];
    const float* state = (const float*)d_in[1];
    const float* x0    = (const float*)d_in[2];
    const float* x1    = (const float*)d_in[3];
    const float* W1    = (const float*)d_in[4];
    const float* b1    = (const float*)d_in[5];
    const float* W2    = (const float*)d_in[6];
    float* out = (float*)d_out;

    k_stage1<<<112,                256>>>(W1, W2, t, state, x0, x1, b1);
    k_A2    <<<dim3(4,4,2*B_+1),   256>>>(W1, W2, state);
    k_nrm   <<<dim3(10,2,B_),      256>>>(state, out);
}

// round 17
// speedup vs baseline: 1.0274x; 1.0274x over previous
#include <cuda_runtime.h>
#include <math.h>

#define N_ 128
#define H_ 256
#define B_ 16

// -------- device scratch --------
__device__ float g_P[H_*H_];        // W1^T W1
__device__ float g_Q[H_*H_];        // W2 W2^T
__device__ float g_s[B_*H_];
__device__ float g_c[B_*H_];
__device__ float g_Avec[B_*N_];
__device__ float g_Cvec[B_*N_];
__device__ float g_vn[B_];
__device__ float g_A2[2*B_*H_*H_];  // split-K partials: [ka*B+b][g][h]
__device__ float g_part[B_*20];     // nrm^2/2 partials: [b][tile*2+ka]
__device__ unsigned int g_cnt[B_];  // last-block-done counters (k_nrm)
__device__ unsigned int g_ready;    // prep-done counter (reset by k_nrm)

#define FFMA2(d, a, b) \
    asm("fma.rn.f32x2 %0, %1, %2, %0;" : "+l"(d) : "l"(a), "l"(b))
#define DUP2(d, f) \
    asm("mov.b64 %0, {%1, %1};" : "=l"(d) : "f"(f))
#define UNPK2(lo, hi, d) \
    asm("mov.b64 {%0, %1}, %2;" : "=f"(lo), "=f"(hi) : "l"(d))

#define MICRO_STEP_F32X2(As_, Bs_)                                      \
    {   float4 ra = *(const float4*)&As_[k][ty*4];                      \
        ulonglong2 rbp = *(const ulonglong2*)&Bs_[k][tx*4];             \
        unsigned long long ad0, ad1, ad2, ad3;                          \
        DUP2(ad0, ra.x); DUP2(ad1, ra.y);                               \
        DUP2(ad2, ra.z); DUP2(ad3, ra.w);                               \
        FFMA2(accp[0][0], ad0, rbp.x); FFMA2(accp[0][1], ad0, rbp.y);   \
        FFMA2(accp[1][0], ad1, rbp.x); FFMA2(accp[1][1], ad1, rbp.y);   \
        FFMA2(accp[2][0], ad2, rbp.x); FFMA2(accp[2][1], ad2, rbp.y);   \
        FFMA2(accp[3][0], ad3, rbp.x); FFMA2(accp[3][1], ad3, rbp.y);   \
    }

#define UNPACK_ACC()                                                    \
    float acc[4][4];                                                    \
    _Pragma("unroll")                                                   \
    for (int i = 0; i < 4; i++){                                        \
        UNPK2(acc[i][0], acc[i][1], accp[i][0]);                        \
        UNPK2(acc[i][2], acc[i][3], accp[i][1]);                        \
    }

#define LOAD16_ROW(dst, ptr)                                            \
    {   float4 t0 = *(const float4*)&(ptr)[0];                          \
        float4 t1 = *(const float4*)&(ptr)[4];                          \
        float4 t2 = *(const float4*)&(ptr)[8];                          \
        float4 t3 = *(const float4*)&(ptr)[12];                         \
        dst[0]=t0.x; dst[1]=t0.y; dst[2]=t0.z; dst[3]=t0.w;             \
        dst[4]=t1.x; dst[5]=t1.y; dst[6]=t1.z; dst[7]=t1.w;             \
        dst[8]=t2.x; dst[9]=t2.y; dst[10]=t2.z; dst[11]=t2.w;           \
        dst[12]=t3.x; dst[13]=t3.y; dst[14]=t3.z; dst[15]=t3.w;         \
    }

#define SIGNAL_READY()                                                  \
    {   __threadfence();                                                \
        __syncthreads();                                                \
        if (tid == 0) atomicAdd(&g_ready, 1u);                          \
    }

#define WAIT_READY()                                                    \
    {   if (tid == 0){                                                  \
            volatile unsigned int* p = &g_ready;                        \
            while (*p != 48u) __nanosleep(64);                          \
        }                                                               \
        __syncthreads();                                                \
        __threadfence();                                                \
    }

// ==================== fused stage 1+2 ====================
// bid 0..31: P/Q tiles (producers); 32..47: s/c/vn (producers);
// 48..63: vector part 2 (consumers); 64..575: split-K A2 GEMM (consumers).
// All 576 blocks are simultaneously resident (4 blocks/SM x 148 = 592), so
// the consumer spin-wait cannot deadlock.
__global__ void __launch_bounds__(256, 4) k_fused(
        const float* __restrict__ W1, const float* __restrict__ W2,
        const float* __restrict__ tptr, const float* __restrict__ state,
        const float* __restrict__ x0,  const float* __restrict__ x1,
        const float* __restrict__ b1){
    int bid = blockIdx.x;
    int tid = threadIdx.x;

    if (bid < 32){
        // ---- P = W1^T W1 (z=0) or Q = W2 W2^T (z=1), double-buffered ----
        int z = bid >> 4, tile = bid & 15;
        int g0 = (tile >> 2)*64, h0 = (tile & 3)*64;
        __shared__ float As[2][16][68];
        __shared__ float Bs[2][16][68];
        int ty = tid >> 4, tx = tid & 15;
        unsigned long long accp[4][2] = {{0ull,0ull},{0ull,0ull},{0ull,0ull},{0ull,0ull}};

        int la = tid >> 4, lq4 = (tid & 15)*4;
        int gg = tid >> 2, kq = (tid & 3)*4;
        float4 av, bv;
        if (z == 0){
            av = *(const float4*)&W1[la*H_ + g0 + lq4];
            bv = *(const float4*)&W1[la*H_ + h0 + lq4];
            *(float4*)&As[0][la][lq4] = av;
            *(float4*)&Bs[0][la][lq4] = bv;
        } else {
            av = *(const float4*)&W2[(g0+gg)*N_ + kq];
            bv = *(const float4*)&W2[(h0+gg)*N_ + kq];
            As[0][kq+0][gg] = av.x; As[0][kq+1][gg] = av.y;
            As[0][kq+2][gg] = av.z; As[0][kq+3][gg] = av.w;
            Bs[0][kq+0][gg] = bv.x; Bs[0][kq+1][gg] = bv.y;
            Bs[0][kq+2][gg] = bv.z; Bs[0][kq+3][gg] = bv.w;
        }
        __syncthreads();

        for (int t = 0; t < 8; t++){
            int cur = t & 1;
            if (t < 7){
                int a0 = (t+1)*16;
                if (z == 0){
                    av = *(const float4*)&W1[(a0+la)*H_ + g0 + lq4];
                    bv = *(const float4*)&W1[(a0+la)*H_ + h0 + lq4];
                } else {
                    av = *(const float4*)&W2[(g0+gg)*N_ + a0 + kq];
                    bv = *(const float4*)&W2[(h0+gg)*N_ + a0 + kq];
                }
            }
            #pragma unroll
            for (int k = 0; k < 16; k++) MICRO_STEP_F32X2(As[cur], Bs[cur])
            if (t < 7){
                if (z == 0){
                    *(float4*)&As[cur^1][la][lq4] = av;
                    *(float4*)&Bs[cur^1][la][lq4] = bv;
                } else {
                    As[cur^1][kq+0][gg] = av.x; As[cur^1][kq+1][gg] = av.y;
                    As[cur^1][kq+2][gg] = av.z; As[cur^1][kq+3][gg] = av.w;
                    Bs[cur^1][kq+0][gg] = bv.x; Bs[cur^1][kq+1][gg] = bv.y;
                    Bs[cur^1][kq+2][gg] = bv.z; Bs[cur^1][kq+3][gg] = bv.w;
                }
            }
            __syncthreads();
        }
        UNPACK_ACC()
        float* dst = (z == 0) ? g_P : g_Q;
        #pragma unroll
        for (int i = 0; i < 4; i++){
            float4 o = make_float4(acc[i][0], acc[i][1], acc[i][2], acc[i][3]);
            *(float4*)&dst[(g0+ty*4+i)*H_ + h0 + tx*4] = o;
        }
        SIGNAL_READY()
        return;
    }

    if (bid < 48){
        // ---- per-sample: x, u = W1^T x, s, c, ||v|| ----
        int b = bid - 32;
        __shared__ float xs[N_], red[N_];
        if (tid == 0) g_cnt[b] = 0;     // reset for k_nrm

        float tval = *tptr;
        float window = 4.f * tval * (1.f - tval);
        if (tid < N_){
            float dev = state[b*N_ + tid];
            float v   = state[(B_+b)*N_ + tid];
            float x0v = x0[b*N_ + tid];
            xs[tid] = x0v + tval*(x1[b*N_ + tid] - x0v) + window*dev;
            red[tid] = v*v;
        }
        __syncthreads();

        if (tid < 32){
            float a0 = red[tid] + red[tid+32] + red[tid+64] + red[tid+96];
            #pragma unroll
            for (int o = 16; o; o >>= 1) a0 += __shfl_xor_sync(0xffffffffu, a0, o);
            if (tid == 0) g_vn[b] = sqrtf(a0);
        }

        int h = tid;
        float u = 0.f;
        for (int k0 = 0; k0 < N_; k0 += 16){
            float wb[16];
            #pragma unroll
            for (int j = 0; j < 16; j++) wb[j] = W1[(k0+j)*H_ + h];
            #pragma unroll
            for (int j = 0; j < 16; j++) u += xs[k0+j]*wb[j];
        }
        float th = tanhf(u + b1[h]);
        float s = 1.f - th*th;
        g_s[b*H_ + h] = s;
        g_c[b*H_ + h] = -2.f*th*s;
        SIGNAL_READY()
        return;
    }

    if (bid < 64){
        // ---- vector part 2: w,y -> z,q2 via P -> pv,cwz -> A,C ----
        int b = bid - 48;
        __shared__ float vs[N_];
        __shared__ float swv[H_], cwy[H_], pvs[H_], cwz[H_];
        __shared__ float Ap[2][N_], Cp[2][N_];

        if (tid < N_) vs[tid] = state[(B_+b)*N_ + tid];
        WAIT_READY()

        int h = tid;
        float s = g_s[b*H_ + h];
        float c = g_c[b*H_ + h];
        float w = 0.f, y = 0.f;
        {
            const float* w2r = W2 + h*N_;
            for (int k0 = 0; k0 < N_; k0 += 16){
                float tb[16], wb[16];
                LOAD16_ROW(tb, (w2r + k0))
                #pragma unroll
                for (int j = 0; j < 16; j++) wb[j] = W1[(k0+j)*H_ + h];
                #pragma unroll
                for (int j = 0; j < 16; j++){
                    w += vs[k0+j]*tb[j];
                    y += vs[k0+j]*wb[j];
                }
            }
        }
        swv[h] = s*w;
        cwy[h] = c*w*y;
        __syncthreads();

        float z = 0.f, q2 = 0.f;
        for (int a0 = 0; a0 < H_; a0 += 16){
            float pb[16];
            #pragma unroll
            for (int j = 0; j < 16; j++) pb[j] = g_P[(a0+j)*H_ + h];
            #pragma unroll
            for (int j = 0; j < 16; j++){
                z  += pb[j]*swv[a0+j];
                q2 += pb[j]*cwy[a0+j];
            }
        }
        pvs[h] = c*y*z + s*q2;
        cwz[h] = c*w*z;
        __syncthreads();

        {
            int i = tid & 127, hf = tid >> 7;
            const float* w1r = W1 + i*H_ + hf*128;
            float A = 0.f, Cc = 0.f;
            for (int j0 = 0; j0 < 128; j0 += 16){
                float wa[16], wc[16];
                #pragma unroll
                for (int j = 0; j < 16; j++) wa[j] = W2[(hf*128 + j0 + j)*N_ + i];
                LOAD16_ROW(wc, (w1r + j0))
                #pragma unroll
                for (int j = 0; j < 16; j++){
                    A  += wa[j]*pvs[hf*128 + j0 + j];
                    Cc += wc[j]*cwz[hf*128 + j0 + j];
                }
            }
            Ap[hf][i] = A;
            Cp[hf][i] = Cc;
        }
        __syncthreads();
        if (tid < N_){
            g_Avec[b*N_ + tid] = Ap[0][tid] + Ap[1][tid];
            g_Cvec[b*N_ + tid] = 2.f*(Cp[0][tid] + Cp[1][tid]);
        }
        return;
    }

    // ---- split-K A2 GEMM (consumer) ----
    int zz = bid - 64;
    int b = zz >> 5;                 // 32 blocks per sample
    int r = zz & 31;                 // ka*16 + tile
    int ka = r >> 4;
    int tile = r & 15;
    int g0 = (tile >> 2)*64, h0 = (tile & 3)*64;
    int ty = tid >> 4, tx = tid & 15;
    __shared__ float Ps[2][16][68];
    __shared__ float Qs[2][16][68];
    __shared__ float ssm[H_];
    unsigned long long accp[4][2] = {{0ull,0ull},{0ull,0ull},{0ull,0ull},{0ull,0ull}};

    WAIT_READY()
    ssm[tid] = g_s[b*H_ + tid];

    int a = tid >> 4, q4 = (tid & 15)*4;
    int abase = ka*128;
    float4 pv = *(const float4*)&g_P[(abase + a)*H_ + g0 + q4];
    float4 qv = *(const float4*)&g_Q[(abase + a)*H_ + h0 + q4];
    __syncthreads();
    {
        float sa = ssm[abase + a];
        *(float4*)&Ps[0][a][q4] = pv;
        qv.x *= sa; qv.y *= sa; qv.z *= sa; qv.w *= sa;
        *(float4*)&Qs[0][a][q4] = qv;
    }
    __syncthreads();

    for (int t = 0; t < 8; t++){
        int cur = t & 1;
        if (t < 7){
            pv = *(const float4*)&g_P[(abase + (t+1)*16 + a)*H_ + g0 + q4];
            qv = *(const float4*)&g_Q[(abase + (t+1)*16 + a)*H_ + h0 + q4];
        }
        #pragma unroll
        for (int k = 0; k < 16; k++) MICRO_STEP_F32X2(Ps[cur], Qs[cur])
        if (t < 7){
            float sa = ssm[abase + (t+1)*16 + a];
            *(float4*)&Ps[cur^1][a][q4] = pv;
            qv.x *= sa; qv.y *= sa; qv.z *= sa; qv.w *= sa;
            *(float4*)&Qs[cur^1][a][q4] = qv;
        }
        __syncthreads();
    }
    UNPACK_ACC()
    float* dst = g_A2 + (ka*B_ + b)*H_*H_;
    #pragma unroll
    for (int i = 0; i < 4; i++){
        float4 o = make_float4(acc[i][0], acc[i][1], acc[i][2], acc[i][3]);
        *(float4*)&dst[(g0+ty*4+i)*H_ + h0 + tx*4] = o;
    }
}

// ========== stage 3: M = P diag(s) A2^T, upper tiles x split-K2, A2 = lo+hi ==========
__global__ void __launch_bounds__(256) k_nrm(const float* __restrict__ state,
                                             float* __restrict__ out){
    const int gt_t[10] = {0,0,0,0,1,1,1,2,2,3};
    const int ht_t[10] = {0,1,2,3,1,2,3,2,3,3};
    int b  = blockIdx.z;
    int ti = blockIdx.x;
    int ka = blockIdx.y;
    int g0 = gt_t[ti]*64, h0 = ht_t[ti]*64;
    int abase = ka*128;
    bool diag = (g0 == h0);
    int tid = threadIdx.x;
    int ty = tid >> 4, tx = tid & 15;
    __shared__ float As[2][16][68];
    __shared__ float Bs[2][16][68];
    __shared__ float Ts[64][65];
    __shared__ float ssm[H_];
    ssm[tid] = g_s[b*H_ + tid];
    unsigned long long accp[4][2] = {{0ull,0ull},{0ull,0ull},{0ull,0ull},{0ull,0ull}};

    const float* A2lo = g_A2 + b*H_*H_;
    const float* A2hi = g_A2 + (B_ + b)*H_*H_;
    int a  = tid >> 4, q4 = (tid & 15)*4;
    int rw = tid >> 2, kq = (tid & 3)*4;

    if (ka == 0){
        #pragma unroll
        for (int p = 0; p < 4; p++){
            int f = tid + p*256;
            int row = f >> 4, c4 = (f & 15)*4;
            float4 tl = *(const float4*)&A2lo[(h0+row)*H_ + g0 + c4];
            float4 thv = *(const float4*)&A2hi[(h0+row)*H_ + g0 + c4];
            Ts[row][c4+0] = tl.x+thv.x; Ts[row][c4+1] = tl.y+thv.y;
            Ts[row][c4+2] = tl.z+thv.z; Ts[row][c4+3] = tl.w+thv.w;
        }
    }

    float4 pv = *(const float4*)&g_P[(abase + a)*H_ + g0 + q4];
    float4 bl = *(const float4*)&A2lo[(h0+rw)*H_ + abase + kq];
    float4 bh = *(const float4*)&A2hi[(h0+rw)*H_ + abase + kq];
    __syncthreads();
    {
        float sa = ssm[abase + a];
        pv.x *= sa; pv.y *= sa; pv.z *= sa; pv.w *= sa;
        *(float4*)&As[0][a][q4] = pv;
        Bs[0][kq+0][rw] = bl.x+bh.x; Bs[0][kq+1][rw] = bl.y+bh.y;
        Bs[0][kq+2][rw] = bl.z+bh.z; Bs[0][kq+3][rw] = bl.w+bh.w;
    }
    __syncthreads();

    for (int t = 0; t < 8; t++){
        int cur = t & 1;
        if (t < 7){
            pv = *(const float4*)&g_P[(abase + (t+1)*16 + a)*H_ + g0 + q4];
            bl = *(const float4*)&A2lo[(h0+rw)*H_ + abase + (t+1)*16 + kq];
            bh = *(const float4*)&A2hi[(h0+rw)*H_ + abase + (t+1)*16 + kq];
        }
        #pragma unroll
        for (int k = 0; k < 16; k++) MICRO_STEP_F32X2(As[cur], Bs[cur])
        if (t < 7){
            float sa = ssm[abase + (t+1)*16 + a];
            pv.x *= sa; pv.y *= sa; pv.z *= sa; pv.w *= sa;
            *(float4*)&As[cur^1][a][q4] = pv;
            Bs[cur^1][kq+0][rw] = bl.x+bh.x; Bs[cur^1][kq+1][rw] = bl.y+bh.y;
            Bs[cur^1][kq+2][rw] = bl.z+bh.z; Bs[cur^1][kq+3][rw] = bl.w+bh.w;
        }
        __syncthreads();
    }
    UNPACK_ACC()

    const float* cb = g_c + b*H_;
    float local = 0.f;
    #pragma unroll
    for (int i = 0; i < 4; i++){
        int g = g0 + ty*4 + i;
        float cg = cb[g];
        float4 P4  = *(const float4*)&g_P[g*H_ + h0 + tx*4];
        float4 Q4  = *(const float4*)&g_Q[g*H_ + h0 + tx*4];
        float pr[4] = {P4.x, P4.y, P4.z, P4.w};
        float qr[4] = {Q4.x, Q4.y, Q4.z, Q4.w};
        if (ka == 0){
            float4 Al = *(const float4*)&A2lo[g*H_ + h0 + tx*4];
            float4 Ah = *(const float4*)&A2hi[g*H_ + h0 + tx*4];
            float ar[4] = {Al.x+Ah.x, Al.y+Ah.y, Al.z+Ah.z, Al.w+Ah.w};
            #pragma unroll
            for (int j = 0; j < 4; j++){
                int hcol = h0 + tx*4 + j;
                float wgt = diag ? ((hcol > g) ? 2.f : ((hcol == g) ? 1.f : 0.f)) : 2.f;
                float a2t = Ts[tx*4+j][ty*4+i];
                local += wgt*cg*cb[hcol]*pr[j]*(qr[j]*acc[i][j] + ar[j]*a2t);
            }
        } else {
            #pragma unroll
            for (int j = 0; j < 4; j++){
                int hcol = h0 + tx*4 + j;
                float wgt = diag ? ((hcol > g) ? 2.f : ((hcol == g) ? 1.f : 0.f)) : 2.f;
                local += wgt*cg*cb[hcol]*pr[j]*qr[j]*acc[i][j];
            }
        }
    }
    __shared__ float red[256];
    red[tid] = local;
    __syncthreads();
    for (int st = 128; st > 0; st >>= 1){
        if (tid < st) red[tid] += red[tid + st];
        __syncthreads();
    }
    __shared__ unsigned int is_last;
    if (tid == 0){
        g_part[b*20 + ti*2 + ka] = red[0];
        __threadfence();
        is_last = (atomicAdd(&g_cnt[b], 1u) == 19u);
    }
    __syncthreads();

    if (is_last){
        if (tid == 0 && b == 0) g_ready = 0;   // reset for next replay
        if (tid < N_){
            float sum = 0.f;
            #pragma unroll
            for (int i = 0; i < 20; i++) sum += g_part[b*20 + i];
            float nrm = sqrtf(fmaxf(2.f*sum, 0.f));
            float vn  = g_vn[b];
            float v   = state[(B_+b)*N_ + tid];
            float dev = state[b*N_ + tid];
            float aout = -(g_Avec[b*N_ + tid] - 0.5f*g_Cvec[b*N_ + tid])
                         / ((nrm + 1e-6f) * (vn + 1e-6f));
            out[b*N_ + tid]       = v;
            out[(B_+b)*N_ + tid]  = aout - 0.1f*dev;
        }
    }
}

// -------- launch --------
extern "C" void kernel_launch(void* const* d_in, const int* in_sizes, int n_in,
                              void* d_out, int out_size){
    const float* t     = (const float*)d_in[0];
    const float* state = (const float*)d_in[1];
    const float* x0    = (const float*)d_in[2];
    const float* x1    = (const float*)d_in[3];
    const float* W1    = (const float*)d_in[4];
    const float* b1    = (const float*)d_in[5];
    const float* W2    = (const float*)d_in[6];
    float* out = (float*)d_out;

    k_fused<<<576,            256>>>(W1, W2, t, state, x0, x1, b1);
    k_nrm  <<<dim3(10,2,B_),  256>>>(state, out);
}